// round 1
// baseline (speedup 1.0000x reference)
#include <cuda_runtime.h>
#include <cstdint>

// Problem-shape upper bounds (this problem: N=100000, E=1600000, E+N=1700000)
#define MAXN 100000
#define MAXE 1700000

// ---------------- device scratch (static, allocation-free) ----------------
__device__ float g_h1[(size_t)MAXN * 64];      // layer-1 transformed features
__device__ float g_asd1[(size_t)MAXN * 2];     // (a_src, a_dst) layer 1
__device__ float g_w[MAXE];                    // exp(logit) per edge (reused both layers)
__device__ float g_denom1[MAXN];
__device__ float g_accum1[(size_t)MAXN * 64];  // layer-1 aggregation
__device__ float g_h3[(size_t)MAXN * 2];       // layer-2 transformed features
__device__ float g_asd2[(size_t)MAXN * 2];
__device__ float g_denom2[MAXN];
__device__ float g_accum2[(size_t)MAXN * 2];
__device__ float g_sum_ea;
__device__ float g_scal[4];                    // {c1, loop_ae1, c2, loop_ae2}

// ---------------- zero-init ----------------
__global__ void zero_kernel(int N) {
    int i = blockIdx.x * blockDim.x + threadIdx.x;
    int total = N * 64;
    if (i < total) g_accum1[i] = 0.f;
    if (i < N) { g_denom1[i] = 0.f; g_denom2[i] = 0.f; }
    if (i < 2 * N) g_accum2[i] = 0.f;
    if (i == 0) g_sum_ea = 0.f;
}

// ---------------- mean(edge_attr) reduction ----------------
__global__ void sum_ea_kernel(const float* __restrict__ ea, int n) {
    __shared__ float sdata[8];
    float s = 0.f;
    for (int i = blockIdx.x * blockDim.x + threadIdx.x; i < n; i += gridDim.x * blockDim.x)
        s += ea[i];
    #pragma unroll
    for (int o = 16; o; o >>= 1) s += __shfl_xor_sync(0xffffffffu, s, o);
    if ((threadIdx.x & 31) == 0) sdata[threadIdx.x >> 5] = s;
    __syncthreads();
    if (threadIdx.x < 8) {
        float v = sdata[threadIdx.x];
        #pragma unroll
        for (int o = 4; o; o >>= 1) v += __shfl_xor_sync(0xffu, v, o);
        if (threadIdx.x == 0) atomicAdd(&g_sum_ea, v);
    }
}

// ---------------- scalar edge constants ----------------
__global__ void scalars_kernel(const float* __restrict__ We1, const float* __restrict__ ae1,
                               const float* __restrict__ We2, const float* __restrict__ ae2,
                               int H, int C, float invE) {
    if (threadIdx.x == 0) {
        float c1 = 0.f;
        for (int k = 0; k < H; k++) c1 += We1[k] * ae1[k];
        float c2 = 0.f;
        for (int k = 0; k < C; k++) c2 += We2[k] * ae2[k];
        float m = g_sum_ea * invE;
        g_scal[0] = c1; g_scal[1] = m * c1;
        g_scal[2] = c2; g_scal[3] = m * c2;
    }
}

// ---------------- SGEMM: h1 = x[M,128] @ W1[128,64] ----------------
// Block: 128 threads, tile 128(M) x 64(N), 8x8 per thread, K-chunks of 16.
__global__ void __launch_bounds__(128) gemm1_kernel(const float* __restrict__ x,
                                                    const float* __restrict__ W, int M) {
    __shared__ float Xs[16][128];
    __shared__ float Ws[16][64];
    const int tid = threadIdx.x;
    const int tr = tid >> 3;        // 0..15 -> 8 rows each
    const int tc = tid & 7;         // 0..7  -> 8 cols each
    const int m0 = blockIdx.x * 128;
    float acc[8][8];
    #pragma unroll
    for (int i = 0; i < 8; i++)
        #pragma unroll
        for (int j = 0; j < 8; j++) acc[i][j] = 0.f;

    for (int k0 = 0; k0 < 128; k0 += 16) {
        // stage X tile: 128 rows x 16 k = 512 float4
        #pragma unroll
        for (int it = 0; it < 4; it++) {
            int f = it * 128 + tid;           // 0..511
            int row = f >> 2;
            int kq = (f & 3) * 4;
            float4 v = make_float4(0.f, 0.f, 0.f, 0.f);
            int gr = m0 + row;
            if (gr < M) v = *(const float4*)&x[(size_t)gr * 128 + k0 + kq];
            Xs[kq + 0][row] = v.x; Xs[kq + 1][row] = v.y;
            Xs[kq + 2][row] = v.z; Xs[kq + 3][row] = v.w;
        }
        // stage W tile: 16 k x 64 cols = 256 float4
        #pragma unroll
        for (int it = 0; it < 2; it++) {
            int f = it * 128 + tid;           // 0..255
            int kk = f >> 4;
            int c4 = (f & 15) * 4;
            *(float4*)&Ws[kk][c4] = *(const float4*)&W[(size_t)(k0 + kk) * 64 + c4];
        }
        __syncthreads();
        #pragma unroll
        for (int kk = 0; kk < 16; kk++) {
            float a[8], b[8];
            *(float4*)&a[0] = *(float4*)&Xs[kk][tr * 8];
            *(float4*)&a[4] = *(float4*)&Xs[kk][tr * 8 + 4];
            *(float4*)&b[0] = *(float4*)&Ws[kk][tc * 8];
            *(float4*)&b[4] = *(float4*)&Ws[kk][tc * 8 + 4];
            #pragma unroll
            for (int i = 0; i < 8; i++)
                #pragma unroll
                for (int j = 0; j < 8; j++) acc[i][j] += a[i] * b[j];
        }
        __syncthreads();
    }
    #pragma unroll
    for (int i = 0; i < 8; i++) {
        int gr = m0 + tr * 8 + i;
        if (gr < M) {
            #pragma unroll
            for (int j4 = 0; j4 < 2; j4++) {
                float4 v = make_float4(acc[i][j4 * 4], acc[i][j4 * 4 + 1],
                                       acc[i][j4 * 4 + 2], acc[i][j4 * 4 + 3]);
                *(float4*)&g_h1[(size_t)gr * 64 + tc * 8 + j4 * 4] = v;
            }
        }
    }
}

// ---------------- per-node attention logit contributions (layer 1) ----------------
__global__ void asd_kernel(const float* __restrict__ att_s, const float* __restrict__ att_d, int N) {
    int warp = (blockIdx.x * blockDim.x + threadIdx.x) >> 5;
    int lane = threadIdx.x & 31;
    if (warp >= N) return;
    float2 v = *(const float2*)&g_h1[(size_t)warp * 64 + lane * 2];
    float as = v.x * att_s[2 * lane] + v.y * att_s[2 * lane + 1];
    float ad = v.x * att_d[2 * lane] + v.y * att_d[2 * lane + 1];
    #pragma unroll
    for (int o = 16; o; o >>= 1) {
        as += __shfl_xor_sync(0xffffffffu, as, o);
        ad += __shfl_xor_sync(0xffffffffu, ad, o);
    }
    if (lane == 0) { g_asd1[2 * warp] = as; g_asd1[2 * warp + 1] = ad; }
}

// ---------------- edge pass 1: w = exp(leaky_relu(logit)); denom[dst] += w ----------------
__global__ void edge_pass1(const int* __restrict__ ei, const float* __restrict__ ea,
                           int E, int N, int layer) {
    int t = blockIdx.x * blockDim.x + threadIdx.x;
    if (t >= E + N) return;
    const float* asd = layer ? g_asd2 : g_asd1;
    float* denom = layer ? g_denom2 : g_denom1;
    float c  = g_scal[layer ? 2 : 0];
    float lp = g_scal[layer ? 3 : 1];
    int s, d; float aev;
    if (t < E) { s = ei[t]; d = ei[E + t]; aev = ea[t] * c; }
    else       { s = d = t - E; aev = lp; }
    float lg = asd[2 * s] + asd[2 * d + 1] + aev;
    lg = lg > 0.f ? lg : 0.2f * lg;
    float wv = __expf(lg);
    g_w[t] = wv;
    atomicAdd(&denom[d], wv);
}

// ---------------- layer-1 aggregation: accum[dst] += alpha * h1[src] (16 lanes/edge) --------
__global__ void edge_aggr64(const int* __restrict__ ei, int E, int N) {
    unsigned t = blockIdx.x * blockDim.x + threadIdx.x;
    unsigned e = t >> 4;
    if (e >= (unsigned)(E + N)) return;
    int j = (int)(t & 15u) * 4;
    int s, d;
    if (e < (unsigned)E) { s = ei[e]; d = ei[E + e]; }
    else                 { s = d = (int)e - E; }
    float alpha = g_w[e] / (g_denom1[d] + 1e-16f);
    float4 hv = *(const float4*)&g_h1[(size_t)s * 64 + j];
    float* p = &g_accum1[(size_t)d * 64 + j];
    asm volatile("red.global.add.v4.f32 [%0], {%1,%2,%3,%4};" ::
                 "l"(p), "f"(alpha * hv.x), "f"(alpha * hv.y),
                 "f"(alpha * hv.z), "f"(alpha * hv.w) : "memory");
}

// ---------------- mid: bias+relu, h3 = h2 @ W2[64,2], a_src2/a_dst2 ----------------
__global__ void mid_kernel(const float* __restrict__ W2, const float* __restrict__ bias1,
                           const float* __restrict__ as2, const float* __restrict__ ad2, int N) {
    int warp = (blockIdx.x * blockDim.x + threadIdx.x) >> 5;
    int lane = threadIdx.x & 31;
    if (warp >= N) return;
    float2 v = *(const float2*)&g_accum1[(size_t)warp * 64 + lane * 2];
    float2 b = *(const float2*)&bias1[lane * 2];
    float v0 = fmaxf(v.x + b.x, 0.f);
    float v1 = fmaxf(v.y + b.y, 0.f);
    float4 w = *(const float4*)&W2[lane * 4];   // rows 2*lane, 2*lane+1 of [64,2]
    float s0 = v0 * w.x + v1 * w.z;
    float s1 = v0 * w.y + v1 * w.w;
    #pragma unroll
    for (int o = 16; o; o >>= 1) {
        s0 += __shfl_xor_sync(0xffffffffu, s0, o);
        s1 += __shfl_xor_sync(0xffffffffu, s1, o);
    }
    if (lane == 0) {
        g_h3[2 * warp] = s0; g_h3[2 * warp + 1] = s1;
        g_asd2[2 * warp]     = s0 * as2[0] + s1 * as2[1];
        g_asd2[2 * warp + 1] = s0 * ad2[0] + s1 * ad2[1];
    }
}

// ---------------- layer-2 aggregation: accum2[dst] += alpha * h3[src] ----------------
__global__ void edge_aggr2(const int* __restrict__ ei, int E, int N) {
    int t = blockIdx.x * blockDim.x + threadIdx.x;
    if (t >= E + N) return;
    int s, d;
    if (t < E) { s = ei[t]; d = ei[E + t]; }
    else       { s = d = t - E; }
    float alpha = g_w[t] / (g_denom2[d] + 1e-16f);
    float2 hv = *(const float2*)&g_h3[2 * s];
    float* p = &g_accum2[2 * d];
    asm volatile("red.global.add.v2.f32 [%0], {%1,%2};" ::
                 "l"(p), "f"(alpha * hv.x), "f"(alpha * hv.y) : "memory");
}

// ---------------- final: bias + log_softmax over 2 classes ----------------
__global__ void final_kernel(const float* __restrict__ bias2, float* __restrict__ out, int N) {
    int i = blockIdx.x * blockDim.x + threadIdx.x;
    if (i >= N) return;
    float o0 = g_accum2[2 * i] + bias2[0];
    float o1 = g_accum2[2 * i + 1] + bias2[1];
    float m = fmaxf(o0, o1);
    float z = logf(expf(o0 - m) + expf(o1 - m));
    out[2 * i] = o0 - m - z;
    out[2 * i + 1] = o1 - m - z;
}

// ---------------- host launcher ----------------
extern "C" void kernel_launch(void* const* d_in, const int* in_sizes, int n_in,
                              void* d_out, int out_size) {
    const float* x   = (const float*)d_in[0];
    const int*   ei  = (const int*)d_in[1];
    const float* ea  = (const float*)d_in[2];
    const float* W1  = (const float*)d_in[3];
    const float* as1 = (const float*)d_in[4];
    const float* ad1 = (const float*)d_in[5];
    const float* We1 = (const float*)d_in[6];
    const float* ae1 = (const float*)d_in[7];
    const float* b1  = (const float*)d_in[8];
    const float* W2  = (const float*)d_in[9];
    const float* as2 = (const float*)d_in[10];
    const float* ad2 = (const float*)d_in[11];
    const float* We2 = (const float*)d_in[12];
    const float* ae2 = (const float*)d_in[13];
    const float* b2  = (const float*)d_in[14];
    float* out = (float*)d_out;

    const int H   = in_sizes[4];          // 64
    const int Fin = in_sizes[3] / H;      // 128
    const int N   = in_sizes[0] / Fin;    // 100000
    const int E   = in_sizes[1] / 2;      // 1600000
    const int C   = in_sizes[10];         // 2
    const int nea = in_sizes[2];          // E * ED

    const int T = 256;

    zero_kernel<<<(N * 64 + T - 1) / T, T>>>(N);
    sum_ea_kernel<<<512, T>>>(ea, nea);
    scalars_kernel<<<1, 32>>>(We1, ae1, We2, ae2, H, C, 1.0f / (float)E);

    gemm1_kernel<<<(N + 127) / 128, 128>>>(x, W1, N);
    asd_kernel<<<(N * 32 + T - 1) / T, T>>>(as1, ad1, N);

    edge_pass1<<<(E + N + T - 1) / T, T>>>(ei, ea, E, N, 0);
    {
        long long tot = (long long)(E + N) * 16;
        edge_aggr64<<<(unsigned)((tot + T - 1) / T), T>>>(ei, E, N);
    }

    mid_kernel<<<(N * 32 + T - 1) / T, T>>>(W2, b1, as2, ad2, N);

    edge_pass1<<<(E + N + T - 1) / T, T>>>(ei, ea, E, N, 1);
    edge_aggr2<<<(E + N + T - 1) / T, T>>>(ei, E, N);

    final_kernel<<<(N + T - 1) / T, T>>>(b2, out, N);
}